// round 3
// baseline (speedup 1.0000x reference)
#include <cuda_runtime.h>

#define N_ATOMS 6144
#define FEAT    128
#define KE_KCAL 332.0637
#define TI 256
#define TJ 256
#define GI (N_ATOMS / TI)            // 24 tiles per side
#define NTRI (GI * (GI + 1) / 2)     // 300 upper-triangle tiles

// Scratch (no device allocation allowed in kernel_launch)
__device__ float  g_pred[N_ATOMS];
__device__ float  g_q[N_ATOMS];
__device__ float4 g_p[N_ATOMS];      // x, y, z, sq
__device__ float  g_corr;
__device__ double g_part[NTRI];      // per-tile energy partials

// ---------------------------------------------------------------------------
// Kernel 1: pred_charge[i] = f[i] . w + z_table[z[i]]   (one warp per atom)
// ---------------------------------------------------------------------------
__global__ __launch_bounds__(256) void k_charge(
    const float* __restrict__ f, const int* __restrict__ z,
    const float* __restrict__ w, const float* __restrict__ ztab)
{
    int gwarp = (blockIdx.x * blockDim.x + threadIdx.x) >> 5;
    int lane  = threadIdx.x & 31;
    if (gwarp >= N_ATOMS) return;
    const float* fr = f + (size_t)gwarp * FEAT;
    float s = 0.f;
#pragma unroll
    for (int c = 0; c < 4; c++)
        s = fmaf(fr[lane + 32 * c], w[lane + 32 * c], s);
#pragma unroll
    for (int o = 16; o; o >>= 1)
        s += __shfl_xor_sync(0xffffffffu, s, o);
    if (lane == 0)
        g_pred[gwarp] = s + ztab[z[gwarp]];
}

// ---------------------------------------------------------------------------
// Kernel 2: correction = (total_charge - sum(pred)) / N    (single block)
// ---------------------------------------------------------------------------
__global__ __launch_bounds__(1024) void k_corr(const float* __restrict__ tc)
{
    __shared__ double ws[32];
    int t = threadIdx.x;
    double s = 0.0;
    for (int i = t; i < N_ATOMS; i += 1024)
        s += (double)g_pred[i];
#pragma unroll
    for (int o = 16; o; o >>= 1)
        s += __shfl_xor_sync(0xffffffffu, s, o);
    if ((t & 31) == 0) ws[t >> 5] = s;
    __syncthreads();
    if (t == 0) {
        double tot = 0.0;
        for (int k = 0; k < 32; k++) tot += ws[k];
        g_corr = (float)(((double)tc[0] - tot) / (double)N_ATOMS);
    }
}

// ---------------------------------------------------------------------------
// Kernel 3: q = pred + corr ; pack {x,y,z,sq} ; write q to output
// ---------------------------------------------------------------------------
__global__ __launch_bounds__(256) void k_q(
    const float* __restrict__ xyz, float* __restrict__ q_out)
{
    int i = blockIdx.x * blockDim.x + threadIdx.x;
    if (i >= N_ATOMS) return;
    float q = g_pred[i] + g_corr;
    g_q[i] = q;
    q_out[i] = q;
    float x = xyz[3 * i + 0], y = xyz[3 * i + 1], zc = xyz[3 * i + 2];
    // EXACT fma ordering reused in the pair kernel so the i==j diagonal
    // cancels to bitwise 0 (matches reference's excluded diagonal).
    float sq = fmaf(zc, zc, fmaf(y, y, x * x));
    g_p[i] = make_float4(x, y, zc, sq);
}

// ---------------------------------------------------------------------------
// Kernel 4: pairwise energy on upper-triangle tiles only (300 of 576).
// Off-diagonal tiles weighted 2x (term is bitwise i<->j symmetric).
// Replicates the reference r2 = sq_i + sq_j - 2*dot formula.
// ---------------------------------------------------------------------------
__global__ __launch_bounds__(TI) void k_pairs()
{
    __shared__ float4 sp[TJ];
    __shared__ float  sqv[TJ];
    __shared__ double wsum[TI / 32];

    // Decode linear tile id -> (bx, by) with bx <= by
    int rem = blockIdx.x, by = 0;
    while (rem > by) { rem -= by + 1; by++; }
    int bx = rem;

    int i  = bx * TI + threadIdx.x;
    int j0 = by * TJ;

    sp[threadIdx.x]  = g_p[j0 + threadIdx.x];
    sqv[threadIdx.x] = g_q[j0 + threadIdx.x];
    __syncthreads();

    float4 pi = g_p[i];
    float  qi = g_q[i];
    float  acc = 0.f;

#pragma unroll 8
    for (int j = 0; j < TJ; j++) {
        float4 pj = sp[j];
        float dot = fmaf(pi.z, pj.z, fmaf(pi.y, pj.y, pi.x * pj.x));
        float r2  = fmaf(-2.f, dot, pi.w + pj.w);
        r2 = fmaxf(r2, 0.f);
        float term = rsqrtf(r2);          // valid common path (r2 >= 56.25)
        if (r2 < 56.25f) {                // rare: switch region / excluded
            term = 0.f;
            if (r2 > 0.f) {
                if (r2 <= 6.25f) {
                    term = rsqrtf(r2 + 1.f);   // fs == 1
                } else {
                    float r   = sqrtf(r2);
                    float arg = (r - 2.5f) * 0.2f;      // (r-R_ON)/(R_OFF-R_ON)
                    float su  = __expf(-1.f / (1.f - arg));
                    float sd  = __expf(-1.f / arg);
                    float fs  = su / (su + sd);
                    term = fs * rsqrtf(r2 + 1.f) + (1.f - fs) / r;
                }
            }
        }
        acc = fmaf(sqv[j], term, acc);
    }
    double a = (double)(acc * qi);
    if (bx != by) a *= 2.0;              // off-diagonal tile counted once

    int lane = threadIdx.x & 31, wid = threadIdx.x >> 5;
#pragma unroll
    for (int o = 16; o; o >>= 1)
        a += __shfl_xor_sync(0xffffffffu, a, o);
    if (lane == 0) wsum[wid] = a;
    __syncthreads();
    if (threadIdx.x == 0) {
        double t = 0.0;
#pragma unroll
        for (int k = 0; k < TI / 32; k++) t += wsum[k];
        g_part[blockIdx.x] = t;
    }
}

// ---------------------------------------------------------------------------
// Kernel 5: final deterministic reduction of tile partials -> energy
// ---------------------------------------------------------------------------
__global__ __launch_bounds__(320) void k_final(float* __restrict__ out)
{
    __shared__ double ws[10];
    int t = threadIdx.x;
    double s = (t < NTRI) ? g_part[t] : 0.0;
#pragma unroll
    for (int o = 16; o; o >>= 1)
        s += __shfl_xor_sync(0xffffffffu, s, o);
    if ((t & 31) == 0) ws[t >> 5] = s;
    __syncthreads();
    if (t == 0) {
        double tot = 0.0;
        for (int k = 0; k < 10; k++) tot += ws[k];
        out[0] = (float)(KE_KCAL * 0.5 * tot);
    }
}

// ---------------------------------------------------------------------------
extern "C" void kernel_launch(void* const* d_in, const int* in_sizes, int n_in,
                              void* d_out, int out_size)
{
    const float* f    = (const float*)d_in[0];
    const int*   z    = (const int*)  d_in[1];
    const float* xyz  = (const float*)d_in[2];
    const float* tc   = (const float*)d_in[3];
    const float* w    = (const float*)d_in[4];
    const float* ztab = (const float*)d_in[5];
    float* out = (float*)d_out;

    k_charge<<<768, 256>>>(f, z, w, ztab);   // one warp per atom
    k_corr<<<1, 1024>>>(tc);
    k_q<<<N_ATOMS / 256, 256>>>(xyz, out + 1);
    k_pairs<<<NTRI, TI>>>();
    k_final<<<1, 320>>>(out);
}

// round 6
// speedup vs baseline: 1.2308x; 1.2308x over previous
#include <cuda_runtime.h>

#define N_ATOMS 6144
#define FEAT    128
#define KE_KCAL 332.0637
#define TB 128                         // tile side / block threads
#define GI (N_ATOMS / TB)              // 48
#define NTRI (GI * (GI + 1) / 2)       // 1176 triangular tiles

__device__ float  g_pred[N_ATOMS];
__device__ float  g_q[N_ATOMS];
__device__ float4 g_p[N_ATOMS];        // x, y, z, sq
__device__ double g_bsum[768];         // per-block pred sums (k_charge)
__device__ double g_part[NTRI];        // per-tile energy partials
__device__ int    g_count = 0;         // last-block-out counter (self-resetting)

// ---------------------------------------------------------------------------
// Kernel 1: pred[i] = f[i].w + z_table[z[i]]  (warp/atom) + per-block sum
// ---------------------------------------------------------------------------
__global__ __launch_bounds__(256) void k_charge(
    const float* __restrict__ f, const int* __restrict__ z,
    const float* __restrict__ w, const float* __restrict__ ztab)
{
    __shared__ double bsum[8];
    int tid   = threadIdx.x;
    int gwarp = (blockIdx.x * 256 + tid) >> 5;
    int lane  = tid & 31;
    const float* fr = f + (size_t)gwarp * FEAT;
    float s = 0.f;
#pragma unroll
    for (int c = 0; c < 4; c++)
        s = fmaf(fr[lane + 32 * c], w[lane + 32 * c], s);
#pragma unroll
    for (int o = 16; o; o >>= 1)
        s += __shfl_xor_sync(0xffffffffu, s, o);
    if (lane == 0) {
        float pred = s + ztab[z[gwarp]];
        g_pred[gwarp] = pred;
        bsum[tid >> 5] = (double)pred;
    }
    __syncthreads();
    if (tid == 0) {
        double t = 0.0;
#pragma unroll
        for (int k = 0; k < 8; k++) t += bsum[k];
        g_bsum[blockIdx.x] = t;
    }
}

// ---------------------------------------------------------------------------
// Kernel 2: every block re-reduces g_bsum identically (deterministic),
//           computes correction, then q + packed {x,y,z,sq}.
// ---------------------------------------------------------------------------
__global__ __launch_bounds__(256) void k_q(
    const float* __restrict__ xyz, const float* __restrict__ tc,
    float* __restrict__ q_out)
{
    __shared__ double ws[8];
    __shared__ float  s_corr;
    int tid = threadIdx.x;

    double s = g_bsum[tid] + g_bsum[tid + 256] + g_bsum[tid + 512];
#pragma unroll
    for (int o = 16; o; o >>= 1)
        s += __shfl_xor_sync(0xffffffffu, s, o);
    if ((tid & 31) == 0) ws[tid >> 5] = s;
    __syncthreads();
    if (tid == 0) {
        double tot = 0.0;
#pragma unroll
        for (int k = 0; k < 8; k++) tot += ws[k];
        s_corr = (float)(((double)tc[0] - tot) / (double)N_ATOMS);
    }
    __syncthreads();

    int i = blockIdx.x * 256 + tid;
    float q = g_pred[i] + s_corr;
    g_q[i] = q;
    q_out[i] = q;
    float x = xyz[3 * i + 0], y = xyz[3 * i + 1], zc = xyz[3 * i + 2];
    // EXACT fma ordering reused in k_pairs so the i==j diagonal cancels to 0.
    float sq = fmaf(zc, zc, fmaf(y, y, x * x));
    g_p[i] = make_float4(x, y, zc, sq);
}

// ---------------------------------------------------------------------------
// Kernel 3: pairwise energy, 128x128 triangular tiles (1176 blocks, 1 wave).
// Off-diagonal tiles weighted 2x (term bitwise i<->j symmetric).
// Last block performs the deterministic final reduction and resets g_count.
// ---------------------------------------------------------------------------
__global__ __launch_bounds__(TB) void k_pairs(float* __restrict__ out)
{
    __shared__ float4 sp[TB];
    __shared__ float  sqv[TB];
    __shared__ double wsum[TB / 32];
    __shared__ int    s_last;

    int tid = threadIdx.x;

    // linear tile id -> (bx, by), bx <= by
    int rem = blockIdx.x, by = 0;
    while (rem > by) { rem -= by + 1; by++; }
    int bx = rem;

    int i  = bx * TB + tid;
    int j0 = by * TB;

    sp[tid]  = g_p[j0 + tid];
    sqv[tid] = g_q[j0 + tid];
    __syncthreads();

    float4 pi = g_p[i];
    float  qi = g_q[i];
    float  acc = 0.f;

#pragma unroll 8
    for (int j = 0; j < TB; j++) {
        float4 pj = sp[j];
        float dot = fmaf(pi.z, pj.z, fmaf(pi.y, pj.y, pi.x * pj.x));
        float r2  = fmaf(-2.f, dot, pi.w + pj.w);
        float term = rsqrtf(r2);          // valid common path (r2 >= 56.25)
        if (!(r2 >= 56.25f)) {            // rare: switch region / excluded / NaN
            term = 0.f;
            if (r2 > 0.f) {
                if (r2 <= 6.25f) {
                    term = rsqrtf(r2 + 1.f);        // fs == 1
                } else {
                    float r   = sqrtf(r2);
                    float arg = (r - 2.5f) * 0.2f;  // (r-R_ON)/(R_OFF-R_ON)
                    float su  = __expf(-1.f / (1.f - arg));
                    float sd  = __expf(-1.f / arg);
                    float fs  = su / (su + sd);
                    term = fs * rsqrtf(r2 + 1.f) + (1.f - fs) / r;
                }
            }
        }
        acc = fmaf(sqv[j], term, acc);
    }
    double a = (double)(acc * qi);
    if (bx != by) a *= 2.0;

    int lane = tid & 31, wid = tid >> 5;
#pragma unroll
    for (int o = 16; o; o >>= 1)
        a += __shfl_xor_sync(0xffffffffu, a, o);
    if (lane == 0) wsum[wid] = a;
    __syncthreads();
    if (tid == 0) {
        double t = 0.0;
#pragma unroll
        for (int k = 0; k < TB / 32; k++) t += wsum[k];
        g_part[blockIdx.x] = t;
        __threadfence();
        int old = atomicAdd(&g_count, 1);
        s_last = (old == NTRI - 1);
    }
    __syncthreads();

    if (s_last) {                         // last block: final reduction
        __threadfence();
        double s = 0.0;
        for (int k = tid; k < NTRI; k += TB)   // fixed order -> deterministic
            s += g_part[k];
#pragma unroll
        for (int o = 16; o; o >>= 1)
            s += __shfl_xor_sync(0xffffffffu, s, o);
        if (lane == 0) wsum[wid] = s;
        __syncthreads();
        if (tid == 0) {
            double tot = 0.0;
#pragma unroll
            for (int k = 0; k < TB / 32; k++) tot += wsum[k];
            out[0] = (float)(KE_KCAL * 0.5 * tot);
            g_count = 0;                  // reset for next graph replay
        }
    }
}

// ---------------------------------------------------------------------------
extern "C" void kernel_launch(void* const* d_in, const int* in_sizes, int n_in,
                              void* d_out, int out_size)
{
    const float* f    = (const float*)d_in[0];
    const int*   z    = (const int*)  d_in[1];
    const float* xyz  = (const float*)d_in[2];
    const float* tc   = (const float*)d_in[3];
    const float* w    = (const float*)d_in[4];
    const float* ztab = (const float*)d_in[5];
    float* out = (float*)d_out;

    k_charge<<<768, 256>>>(f, z, w, ztab);
    k_q<<<N_ATOMS / 256, 256>>>(xyz, tc, out + 1);
    k_pairs<<<NTRI, TB>>>(out);
}

// round 9
// speedup vs baseline: 1.3457x; 1.0934x over previous
#include <cuda_runtime.h>

#define N_ATOMS 6144
#define FEAT    128
#define KE_KCAL 332.0637
#define TB 128                         // tile side / block threads
#define GI (N_ATOMS / TB)              // 48
#define NTRI (GI * (GI + 1) / 2)       // 1176 triangular tiles

__device__ float  g_pred[N_ATOMS];
__device__ float  g_q[N_ATOMS];
__device__ float4 g_p[N_ATOMS];        // x, y, z, sq
__device__ double g_bsum[768];         // per-block pred sums (k_charge)
__device__ double g_part[NTRI];        // per-tile energy partials
__device__ int    g_count = 0;         // last-block-out counter (self-resetting)

// ---------------------------------------------------------------------------
// Kernel 1: pred[i] = f[i].w + z_table[z[i]]  (warp/atom, float4 loads)
// ---------------------------------------------------------------------------
__global__ __launch_bounds__(256) void k_charge(
    const float4* __restrict__ f4, const int* __restrict__ z,
    const float4* __restrict__ w4, const float* __restrict__ ztab)
{
    __shared__ double bsum[8];
    int tid   = threadIdx.x;
    int gwarp = (blockIdx.x * 256 + tid) >> 5;
    int lane  = tid & 31;
    float4 a = f4[(size_t)gwarp * (FEAT / 4) + lane];   // 16B/lane = 128 floats/warp
    float4 b = w4[lane];
    float s = fmaf(a.w, b.w, fmaf(a.z, b.z, fmaf(a.y, b.y, a.x * b.x)));
#pragma unroll
    for (int o = 16; o; o >>= 1)
        s += __shfl_xor_sync(0xffffffffu, s, o);
    if (lane == 0) {
        float pred = s + ztab[z[gwarp]];
        g_pred[gwarp] = pred;
        bsum[tid >> 5] = (double)pred;
    }
    __syncthreads();
    if (tid == 0) {
        double t = 0.0;
#pragma unroll
        for (int k = 0; k < 8; k++) t += bsum[k];
        g_bsum[blockIdx.x] = t;
    }
}

// ---------------------------------------------------------------------------
// Kernel 2: every block re-reduces g_bsum identically (deterministic),
//           computes correction, then q + packed {x,y,z,sq}.
// ---------------------------------------------------------------------------
__global__ __launch_bounds__(256) void k_q(
    const float* __restrict__ xyz, const float* __restrict__ tc,
    float* __restrict__ q_out)
{
    __shared__ double ws[8];
    __shared__ float  s_corr;
    int tid = threadIdx.x;

    double s = g_bsum[tid] + g_bsum[tid + 256] + g_bsum[tid + 512];
#pragma unroll
    for (int o = 16; o; o >>= 1)
        s += __shfl_xor_sync(0xffffffffu, s, o);
    if ((tid & 31) == 0) ws[tid >> 5] = s;
    __syncthreads();
    if (tid == 0) {
        double tot = 0.0;
#pragma unroll
        for (int k = 0; k < 8; k++) tot += ws[k];
        s_corr = (float)(((double)tc[0] - tot) / (double)N_ATOMS);
    }
    __syncthreads();

    int i = blockIdx.x * 256 + tid;
    float q = g_pred[i] + s_corr;
    g_q[i] = q;
    q_out[i] = q;
    float x = xyz[3 * i + 0], y = xyz[3 * i + 1], zc = xyz[3 * i + 2];
    // EXACT fma ordering reused in k_pairs so the i==j diagonal cancels to 0.
    float sq = fmaf(zc, zc, fmaf(y, y, x * x));
    g_p[i] = make_float4(x, y, zc, sq);
}

// ---------------------------------------------------------------------------
// Kernel 3: pairwise energy, 128x128 triangular tiles (1176 blocks, 1 wave).
// __ballot_sync forces a REAL branch around the switch-region fixup so the
// common path is ~14 instr; slow path uses only MUFU-based fast intrinsics.
// Off-diagonal tiles weighted 2x (term bitwise i<->j symmetric).
// ---------------------------------------------------------------------------
__global__ __launch_bounds__(TB) void k_pairs(float* __restrict__ out)
{
    __shared__ float4 sp[TB];
    __shared__ float  sqv[TB];
    __shared__ double wsum[TB / 32];
    __shared__ int    s_last;

    int tid = threadIdx.x;

    // linear tile id -> (bx, by), bx <= by
    int rem = blockIdx.x, by = 0;
    while (rem > by) { rem -= by + 1; by++; }
    int bx = rem;

    int i  = bx * TB + tid;
    int j0 = by * TB;

    sp[tid]  = g_p[j0 + tid];
    sqv[tid] = g_q[j0 + tid];
    __syncthreads();

    float4 pi = g_p[i];
    float  qi = g_q[i];
    float  acc = 0.f;

#pragma unroll 8
    for (int j = 0; j < TB; j++) {
        float4 pj = sp[j];
        float dot = fmaf(pi.z, pj.z, fmaf(pi.y, pj.y, pi.x * pj.x));
        float r2  = fmaf(-2.f, dot, pi.w + pj.w);
        float term = rsqrtf(r2);            // valid when r2 >= 56.25 (~99.2%)
        bool  fix  = !(r2 >= 56.25f);       // switch region / excluded / NaN
        if (__ballot_sync(0xffffffffu, fix)) {   // real branch, warp-skipped
            if (fix) {
                term = 0.f;
                if (r2 > 0.f) {
                    if (r2 <= 6.25f) {
                        term = rsqrtf(r2 + 1.f);         // fs == 1
                    } else {
                        float r   = sqrtf(r2);
                        float arg = (r - 2.5f) * 0.2f;   // in (0,1)
                        float su  = __expf(-__fdividef(1.f, 1.f - arg));
                        float sd  = __expf(-__fdividef(1.f, arg));
                        float fs  = __fdividef(su, su + sd);
                        term = fmaf(fs, rsqrtf(r2 + 1.f),
                                    (1.f - fs) * rsqrtf(r2));
                    }
                }
            }
        }
        acc = fmaf(sqv[j], term, acc);
    }
    double a = (double)(acc * qi);
    if (bx != by) a *= 2.0;

    int lane = tid & 31, wid = tid >> 5;
#pragma unroll
    for (int o = 16; o; o >>= 1)
        a += __shfl_xor_sync(0xffffffffu, a, o);
    if (lane == 0) wsum[wid] = a;
    __syncthreads();
    if (tid == 0) {
        double t = 0.0;
#pragma unroll
        for (int k = 0; k < TB / 32; k++) t += wsum[k];
        g_part[blockIdx.x] = t;
        __threadfence();
        int old = atomicAdd(&g_count, 1);
        s_last = (old == NTRI - 1);
    }
    __syncthreads();

    if (s_last) {                          // last block: final reduction
        __threadfence();
        double s = 0.0;
        for (int k = tid; k < NTRI; k += TB)   // fixed order -> deterministic
            s += g_part[k];
#pragma unroll
        for (int o = 16; o; o >>= 1)
            s += __shfl_xor_sync(0xffffffffu, s, o);
        if (lane == 0) wsum[wid] = s;
        __syncthreads();
        if (tid == 0) {
            double tot = 0.0;
#pragma unroll
            for (int k = 0; k < TB / 32; k++) tot += wsum[k];
            out[0] = (float)(KE_KCAL * 0.5 * tot);
            g_count = 0;                   // reset for next graph replay
        }
    }
}

// ---------------------------------------------------------------------------
extern "C" void kernel_launch(void* const* d_in, const int* in_sizes, int n_in,
                              void* d_out, int out_size)
{
    const float* f    = (const float*)d_in[0];
    const int*   z    = (const int*)  d_in[1];
    const float* xyz  = (const float*)d_in[2];
    const float* tc   = (const float*)d_in[3];
    const float* w    = (const float*)d_in[4];
    const float* ztab = (const float*)d_in[5];
    float* out = (float*)d_out;

    k_charge<<<768, 256>>>((const float4*)f, z, (const float4*)w, ztab);
    k_q<<<N_ATOMS / 256, 256>>>(xyz, tc, out + 1);
    k_pairs<<<NTRI, TB>>>(out);
}

// round 10
// speedup vs baseline: 1.7724x; 1.3171x over previous
#include <cuda_runtime.h>

#define N_ATOMS 6144
#define FEAT    128
#define KE_KCAL 332.0637
#define TB 128                         // tile side / block threads
#define GI (N_ATOMS / TB)              // 48
#define NTRI (GI * (GI + 1) / 2)       // 1176 triangular tiles

__device__ float  g_pred[N_ATOMS];
__device__ float  g_q[N_ATOMS];
__device__ float4 g_p[N_ATOMS];        // x, y, z, sq
__device__ double g_bsum[384];         // per-block pred sums (k_charge)
__device__ double g_part[NTRI];        // per-tile energy partials
__device__ int    g_count = 0;         // last-block-out counter (self-resetting)

// ---------------------------------------------------------------------------
// Kernel 1: pred[i] = f[i].w + z_table[z[i]]  (2 atoms per warp for MLP)
// ---------------------------------------------------------------------------
__global__ __launch_bounds__(256) void k_charge(
    const float4* __restrict__ f4, const int* __restrict__ z,
    const float4* __restrict__ w4, const float* __restrict__ ztab)
{
    __shared__ double bsum[8];
    int tid   = threadIdx.x;
    int gwarp = (blockIdx.x * 256 + tid) >> 5;
    int lane  = tid & 31;
    int a0 = gwarp * 2, a1 = a0 + 1;
    float4 va = f4[(size_t)a0 * (FEAT / 4) + lane];
    float4 vb = f4[(size_t)a1 * (FEAT / 4) + lane];
    float4 wv = w4[lane];
    float s0 = fmaf(va.w, wv.w, fmaf(va.z, wv.z, fmaf(va.y, wv.y, va.x * wv.x)));
    float s1 = fmaf(vb.w, wv.w, fmaf(vb.z, wv.z, fmaf(vb.y, wv.y, vb.x * wv.x)));
#pragma unroll
    for (int o = 16; o; o >>= 1) {
        s0 += __shfl_xor_sync(0xffffffffu, s0, o);
        s1 += __shfl_xor_sync(0xffffffffu, s1, o);
    }
    if (lane == 0) {
        float p0 = s0 + ztab[z[a0]];
        float p1 = s1 + ztab[z[a1]];
        g_pred[a0] = p0;
        g_pred[a1] = p1;
        bsum[tid >> 5] = (double)p0 + (double)p1;
    }
    __syncthreads();
    if (tid == 0) {
        double t = 0.0;
#pragma unroll
        for (int k = 0; k < 8; k++) t += bsum[k];
        g_bsum[blockIdx.x] = t;
    }
}

// ---------------------------------------------------------------------------
// Kernel 2: every block re-reduces g_bsum identically (deterministic),
//           computes correction, then q + packed {x,y,z,sq}.
// ---------------------------------------------------------------------------
__global__ __launch_bounds__(256) void k_q(
    const float* __restrict__ xyz, const float* __restrict__ tc,
    float* __restrict__ q_out)
{
    __shared__ double ws[8];
    __shared__ float  s_corr;
    int tid = threadIdx.x;

    double s = g_bsum[tid] + ((tid < 128) ? g_bsum[tid + 256] : 0.0);
#pragma unroll
    for (int o = 16; o; o >>= 1)
        s += __shfl_xor_sync(0xffffffffu, s, o);
    if ((tid & 31) == 0) ws[tid >> 5] = s;
    __syncthreads();
    if (tid == 0) {
        double tot = 0.0;
#pragma unroll
        for (int k = 0; k < 8; k++) tot += ws[k];
        s_corr = (float)(((double)tc[0] - tot) / (double)N_ATOMS);
    }
    __syncthreads();

    int i = blockIdx.x * 256 + tid;
    float q = g_pred[i] + s_corr;
    g_q[i] = q;
    q_out[i] = q;
    float x = xyz[3 * i + 0], y = xyz[3 * i + 1], zc = xyz[3 * i + 2];
    // EXACT fma ordering reused in k_pairs so the i==j diagonal cancels to 0.
    float sq = fmaf(zc, zc, fmaf(y, y, x * x));
    g_p[i] = make_float4(x, y, zc, sq);
}

// ---------------------------------------------------------------------------
// Dummy kernel: aligns the ncu capture (4th launch) onto k_pairs.
// ---------------------------------------------------------------------------
__global__ void k_dummy() {}

// ---------------------------------------------------------------------------
// Kernel 3: pairwise energy, 128x128 triangular tiles (1176 blocks, 1 wave).
// BRANCH-FREE main loop: accumulate q_j*rsqrtf(max(r2,1e-6)) for every pair
// and record rare pairs (r2<56.25: switch region / diagonal / negative) in a
// per-thread bitmask; a short per-lane fixup loop after each 32-j chunk
// subtracts the bitwise-identical bogus term and adds the reference term.
// Off-diagonal tiles weighted 2x (term bitwise i<->j symmetric).
// ---------------------------------------------------------------------------
__global__ __launch_bounds__(TB) void k_pairs(float* __restrict__ out)
{
    __shared__ float4 sp[TB];
    __shared__ float  sqv[TB];
    __shared__ double wsum[TB / 32];
    __shared__ int    s_last;

    int tid = threadIdx.x;

    // linear tile id -> (bx, by), bx <= by
    int rem = blockIdx.x, by = 0;
    while (rem > by) { rem -= by + 1; by++; }
    int bx = rem;

    int i  = bx * TB + tid;
    int j0 = by * TB;

    sp[tid]  = g_p[j0 + tid];
    sqv[tid] = g_q[j0 + tid];
    __syncthreads();

    float4 pi = g_p[i];
    float  qi = g_q[i];
    float  acc = 0.f;

#pragma unroll
    for (int w = 0; w < 4; w++) {
        unsigned m = 0;
#pragma unroll
        for (int b = 0; b < 32; b++) {
            int j = w * 32 + b;
            float4 pj = sp[j];
            float dot = fmaf(pi.z, pj.z, fmaf(pi.y, pj.y, pi.x * pj.x));
            float r2  = fmaf(-2.f, dot, pi.w + pj.w);
            float r2e = fmaxf(r2, 1e-6f);         // diagonal/negative -> finite
            if (r2e < 56.25f) m |= (1u << b);     // predicated OR, no branch
            acc = fmaf(sqv[j], rsqrtf(r2e), acc); // common path, bitwise as ref
        }
        // Fixup: lanes walk their own (rare) bits concurrently.
        while (m) {
            int b = __ffs(m) - 1;
            m &= m - 1;
            int j = w * 32 + b;
            float4 pj = sp[j];
            float dot = fmaf(pi.z, pj.z, fmaf(pi.y, pj.y, pi.x * pj.x));
            float r2  = fmaf(-2.f, dot, pi.w + pj.w);
            float r2e = fmaxf(r2, 1e-6f);
            acc = fmaf(-sqv[j], rsqrtf(r2e), acc);   // remove bogus term
            if (r2 > 0.f) {                           // reference mask
                float term;
                if (r2 <= 6.25f) {
                    term = rsqrtf(r2 + 1.f);          // fs == 1
                } else {
                    float r   = sqrtf(r2);
                    float arg = (r - 2.5f) * 0.2f;    // in (0,1)
                    float su  = __expf(-__fdividef(1.f, 1.f - arg));
                    float sd  = __expf(-__fdividef(1.f, arg));
                    float fs  = __fdividef(su, su + sd);
                    term = fmaf(fs, rsqrtf(r2 + 1.f), (1.f - fs) * rsqrtf(r2));
                }
                acc = fmaf(sqv[j], term, acc);
            }
        }
    }
    double a = (double)(acc * qi);
    if (bx != by) a *= 2.0;

    int lane = tid & 31, wid = tid >> 5;
#pragma unroll
    for (int o = 16; o; o >>= 1)
        a += __shfl_xor_sync(0xffffffffu, a, o);
    if (lane == 0) wsum[wid] = a;
    __syncthreads();
    if (tid == 0) {
        double t = 0.0;
#pragma unroll
        for (int k = 0; k < TB / 32; k++) t += wsum[k];
        g_part[blockIdx.x] = t;
        __threadfence();
        int old = atomicAdd(&g_count, 1);
        s_last = (old == NTRI - 1);
    }
    __syncthreads();

    if (s_last) {                          // last block: final reduction
        __threadfence();
        double s = 0.0;
        for (int k = tid; k < NTRI; k += TB)   // fixed order -> deterministic
            s += g_part[k];
#pragma unroll
        for (int o = 16; o; o >>= 1)
            s += __shfl_xor_sync(0xffffffffu, s, o);
        if (lane == 0) wsum[wid] = s;
        __syncthreads();
        if (tid == 0) {
            double tot = 0.0;
#pragma unroll
            for (int k = 0; k < TB / 32; k++) tot += wsum[k];
            out[0] = (float)(KE_KCAL * 0.5 * tot);
            g_count = 0;                   // reset for next graph replay
        }
    }
}

// ---------------------------------------------------------------------------
extern "C" void kernel_launch(void* const* d_in, const int* in_sizes, int n_in,
                              void* d_out, int out_size)
{
    const float* f    = (const float*)d_in[0];
    const int*   z    = (const int*)  d_in[1];
    const float* xyz  = (const float*)d_in[2];
    const float* tc   = (const float*)d_in[3];
    const float* w    = (const float*)d_in[4];
    const float* ztab = (const float*)d_in[5];
    float* out = (float*)d_out;

    k_charge<<<384, 256>>>((const float4*)f, z, (const float4*)w, ztab);
    k_q<<<N_ATOMS / 256, 256>>>(xyz, tc, out + 1);
    k_dummy<<<1, 32>>>();                  // profiling alignment (capture = launch #4)
    k_pairs<<<NTRI, TB>>>(out);
}